// round 4
// baseline (speedup 1.0000x reference)
#include <cuda_runtime.h>
#include <cstdint>

#define FULL_MASK 0xFFFFFFFFu
#define KPL 8                 // timesteps per lane
#define SEG (32 * KPL)        // 256 timesteps per warp-segment
#define WPB 4                 // warps per block
#define PAD_W 9               // padded smem words per lane (conflict-free)

// fast sigmoid: 1/(1+e^-x) via MUFU (EX2 + RCP). rel err ~2^-21, far under tol.
__device__ __forceinline__ float fsigmoid(float x) {
    float e = __expf(-x);
    return __fdividef(1.0f, 1.0f + e);
}

// One warp per batch row. Backward affine scan:
//   x_t = A_t * x_{t+1} + B_t,   A_t = g*(1-d_t)*l_t  (shared by both recurrences)
// Software-pipelined: segment s-1's global loads are issued before segment s's
// shuffle scan, hiding DRAM latency behind compute.
__global__ __launch_bounds__(WPB * 32)
void td_scan_kernel(const float* __restrict__ values,    // [B, T+1]
                    const float* __restrict__ rewards,   // [B, T]
                    const float* __restrict__ dones,     // [B, T]
                    const float* __restrict__ raw_gamma, // [1]
                    const float* __restrict__ raw_lambd, // [>=T]
                    const int*   __restrict__ p_start,   // [1] or null
                    float* __restrict__ out_lam,         // [B, T+1]
                    float* __restrict__ out_sum,         // [B, T]
                    int B, int T)
{
    __shared__ float stage[WPB][32 * PAD_W];

    const int lane = threadIdx.x & 31;
    const int wid  = threadIdx.x >> 5;
    const int row  = blockIdx.x * WPB + wid;
    if (row >= B) return;

    const int s0 = p_start ? p_start[0] : 0;
    // gamma = 0.99 + 0.01*(2*sig-1) = 0.98 + 0.02*sig
    const float g = 0.98f + 0.02f * fsigmoid(__ldg(raw_gamma));

    float* st = stage[wid];
    const float* vrow = values  + (size_t)row * (size_t)(T + 1);
    const float* rrow = rewards + (size_t)row * (size_t)T;
    const float* drow = dones   + (size_t)row * (size_t)T;
    float* lrow = out_lam + (size_t)row * (size_t)(T + 1);
    float* srow = out_sum + (size_t)row * (size_t)T;

    const float vlast = vrow[T];
    if (lane == 0) lrow[T] = vlast;

    float c_lam = vlast;
    float c_sum = 0.0f;

    const int nseg = (T + SEG - 1) / SEG;

    // ---- full-segment load (r/d vectorized; values coalesced scalar) ----
    auto load_full = [&](int seg, float4& ra, float4& rb,
                         float4& da, float4& db, float* vt) {
        const int base = seg * SEG + lane * KPL;
        const float4* r4 = (const float4*)(rrow + base);
        ra = r4[0]; rb = r4[1];
        const float4* d4 = (const float4*)(drow + base);
        da = d4[0]; db = d4[1];
        const float* vp = vrow + seg * SEG + 1;
        #pragma unroll
        for (int k = 0; k < 8; k++) vt[k] = __ldg(vp + k * 32 + lane);
    };

    // ---- scan + expand + carry update (data already in A/Bl/Bs) ----
    auto scan_expand = [&](float A[KPL], float Bl[KPL], float Bs[KPL],
                           float outl[KPL], float outs[KPL]) {
        // local composition: S = m_0 ∘ ... ∘ m_{KPL-1}
        float SA = A[KPL - 1], SBl = Bl[KPL - 1], SBs = Bs[KPL - 1];
        #pragma unroll
        for (int j = KPL - 2; j >= 0; --j) {
            SBl = fmaf(A[j], SBl, Bl[j]);
            SBs = fmaf(A[j], SBs, Bs[j]);
            SA  = A[j] * SA;
        }
        // warp inclusive suffix scan
        #pragma unroll
        for (int len = 1; len < 32; len <<= 1) {
            float Ao  = __shfl_down_sync(FULL_MASK, SA,  len);
            float Blo = __shfl_down_sync(FULL_MASK, SBl, len);
            float Bso = __shfl_down_sync(FULL_MASK, SBs, len);
            if (lane + len < 32) {
                SBl = fmaf(SA, Blo, SBl);
                SBs = fmaf(SA, Bso, SBs);
                SA  = SA * Ao;
            }
        }
        // incoming state for this lane
        float nA  = __shfl_down_sync(FULL_MASK, SA,  1);
        float nBl = __shfl_down_sync(FULL_MASK, SBl, 1);
        float nBs = __shfl_down_sync(FULL_MASK, SBs, 1);
        float xl = (lane == 31) ? c_lam : fmaf(nA, c_lam, nBl);
        float xs = (lane == 31) ? c_sum : fmaf(nA, c_sum, nBs);
        // local expansion
        #pragma unroll
        for (int j = KPL - 1; j >= 0; --j) {
            xl = fmaf(A[j], xl, Bl[j]);
            xs = fmaf(A[j], xs, Bs[j]);
            outl[j] = xl;
            outs[j] = xs;
        }
        c_lam = __shfl_sync(FULL_MASK, xl, 0);
        c_sum = __shfl_sync(FULL_MASK, xs, 0);
    };

    // ---- process one FULL segment whose loads are already in registers ----
    auto process_full = [&](int segb, float4 ra, float4 rb,
                            float4 da, float4 db, const float* vt) {
        // transpose values window through padded smem
        #pragma unroll
        for (int k = 0; k < 8; k++) {
            int i = k * 32 + lane;
            st[(i >> 3) * PAD_W + (i & 7)] = vt[k];
        }
        __syncwarp();
        float vn[KPL];
        #pragma unroll
        for (int j = 0; j < KPL; j++) vn[j] = st[lane * PAD_W + j];
        __syncwarp();

        const int base = segb + lane * KPL;
        float r[KPL] = {ra.x, ra.y, ra.z, ra.w, rb.x, rb.y, rb.z, rb.w};
        float d[KPL] = {da.x, da.y, da.z, da.w, db.x, db.y, db.z, db.w};

        float A[KPL], Bl[KPL], Bs[KPL];
        #pragma unroll
        for (int j = 0; j < KPL; j++) {
            // lambda = 0.95 + 0.05*(2*sig-1) = 0.9 + 0.1*sig (L1-hot loads)
            float l = fmaf(0.1f, fsigmoid(__ldg(raw_lambd + s0 + base + j)), 0.9f);
            float cont = g - g * d[j];               // gamma*(1-done)
            A[j]  = cont * l;
            Bl[j] = fmaf(cont - A[j], vn[j], r[j]);  // cont*(1-l)*vn + r
            Bs[j] = r[j];
        }

        float outl[KPL], outs[KPL];
        scan_expand(A, Bl, Bs, outl, outs);

        // sum rows aligned -> STG.128
        float4* s4 = (float4*)(srow + base);
        s4[0] = make_float4(outs[0], outs[1], outs[2], outs[3]);
        s4[1] = make_float4(outs[4], outs[5], outs[6], outs[7]);

        // lam rows misaligned -> transpose via smem, coalesced STG.32
        #pragma unroll
        for (int j = 0; j < KPL; j++) st[lane * PAD_W + j] = outl[j];
        __syncwarp();
        float* lp = lrow + segb;
        #pragma unroll
        for (int k = 0; k < 8; k++) {
            int i = k * 32 + lane;
            lp[i] = st[(i >> 3) * PAD_W + (i & 7)];
        }
        __syncwarp();
    };

    int s = nseg - 1;

    // Peel a partial last segment (only segment nseg-1 can be partial).
    if (nseg * SEG > T) {
        const int base = s * SEG + lane * KPL;
        float A[KPL], Bl[KPL], Bs[KPL];
        #pragma unroll
        for (int j = 0; j < KPL; j++) {
            int t = base + j;
            if (t < T) {
                float r  = rrow[t];
                float d  = drow[t];
                float vn = vrow[t + 1];
                float l  = fmaf(0.1f, fsigmoid(__ldg(raw_lambd + s0 + t)), 0.9f);
                float cont = g - g * d;
                A[j]  = cont * l;
                Bl[j] = fmaf(cont - A[j], vn, r);
                Bs[j] = r;
            } else {
                A[j] = 1.0f; Bl[j] = 0.0f; Bs[j] = 0.0f;
            }
        }
        float outl[KPL], outs[KPL];
        scan_expand(A, Bl, Bs, outl, outs);
        #pragma unroll
        for (int j = 0; j < KPL; j++) {
            if (base + j < T) { lrow[base + j] = outl[j]; srow[base + j] = outs[j]; }
        }
        s--;
    }

    if (s >= 0) {
        // software-pipelined mainloop over full segments
        float4 ra, rb, da, db; float vt[8];
        load_full(s, ra, rb, da, db, vt);
        while (true) {
            float4 nra, nrb, nda, ndb; float nvt[8];
            if (s > 0) load_full(s - 1, nra, nrb, nda, ndb, nvt);  // prefetch
            process_full(s * SEG, ra, rb, da, db, vt);
            if (s == 0) break;
            ra = nra; rb = nrb; da = nda; db = ndb;
            #pragma unroll
            for (int k = 0; k < 8; k++) vt[k] = nvt[k];
            s--;
        }
    }
}

extern "C" void kernel_launch(void* const* d_in, const int* in_sizes, int n_in,
                              void* d_out, int out_size)
{
    const float* values    = (const float*)d_in[0];
    const float* rewards   = (const float*)d_in[1];
    const float* dones     = (const float*)d_in[2];
    const float* raw_gamma = (const float*)d_in[3];
    const float* raw_lambd = (const float*)d_in[4];
    const int*   p_start   = (n_in > 5) ? (const int*)d_in[5] : nullptr;

    const int T = in_sizes[4];
    const int B = in_sizes[1] / T;

    float* out_lam = (float*)d_out;                       // B*(T+1)
    float* out_sum = (float*)d_out + (size_t)B * (T + 1); // B*T

    const int threads = WPB * 32;
    const int blocks  = (B + WPB - 1) / WPB;

    td_scan_kernel<<<blocks, threads>>>(
        values, rewards, dones, raw_gamma, raw_lambd, p_start,
        out_lam, out_sum, B, T);
}

// round 5
// speedup vs baseline: 1.0727x; 1.0727x over previous
#include <cuda_runtime.h>
#include <cstdint>

#define FULL_MASK 0xFFFFFFFFu
#define KPL 8                 // timesteps per lane
#define SEG (32 * KPL)        // 256 timesteps per warp-segment
#define WPB 4                 // warps per block
#define PAD_W 9               // padded smem words per lane (conflict-free)

// fast sigmoid via MUFU (EX2 + RCP); rel err ~1e-6, far under 1e-3 tol.
__device__ __forceinline__ float fsigmoid(float x) {
    return __fdividef(1.0f, 1.0f + __expf(-x));
}

// One warp per batch row. Backward affine scan:
//   x_t = A_t * x_{t+1} + B_t,   A_t = g*(1-d_t)*l_t  (shared by both recurrences)
__global__ __launch_bounds__(WPB * 32)
void td_scan_kernel(const float* __restrict__ values,    // [B, T+1]
                    const float* __restrict__ rewards,   // [B, T]
                    const float* __restrict__ dones,     // [B, T]
                    const float* __restrict__ raw_gamma, // [1]
                    const float* __restrict__ raw_lambd, // [>=T]
                    const int*   __restrict__ p_start,   // [1] or null
                    float* __restrict__ out_lam,         // [B, T+1]
                    float* __restrict__ out_sum,         // [B, T]
                    int B, int T)
{
    __shared__ float stage[WPB][32 * PAD_W];
    extern __shared__ float s_lam[];   // QMAX*8 floats, transposed lambda table

    const int lane = threadIdx.x & 31;
    const int wid  = threadIdx.x >> 5;
    const int row  = blockIdx.x * WPB + wid;

    const int QMAX = (T + 7) >> 3;
    const int s0 = p_start ? p_start[0] : 0;

    // Per-block lambda table, transposed for conflict-free per-lane reads:
    //   t = q*8 + r  ->  s_lam[r*QMAX + q]
    // lambda = 0.95 + 0.05*(2*sig-1) = 0.9 + 0.1*sigmoid(x)
    for (int t = threadIdx.x; t < T; t += blockDim.x) {
        float l = fmaf(0.1f, fsigmoid(__ldg(raw_lambd + s0 + t)), 0.9f);
        s_lam[(t & 7) * QMAX + (t >> 3)] = l;
    }
    __syncthreads();

    if (row >= B) return;

    // gamma = 0.99 + 0.01*(2*sig-1) = 0.98 + 0.02*sigmoid
    const float g = 0.98f + 0.02f * fsigmoid(__ldg(raw_gamma));

    float* st = stage[wid];
    const float* vrow = values  + (size_t)row * (size_t)(T + 1);
    const float* rrow = rewards + (size_t)row * (size_t)T;
    const float* drow = dones   + (size_t)row * (size_t)T;
    float* lrow = out_lam + (size_t)row * (size_t)(T + 1);
    float* srow = out_sum + (size_t)row * (size_t)T;

    const float vlast = vrow[T];
    if (lane == 0) lrow[T] = vlast;

    float c_lam = vlast;
    float c_sum = 0.0f;

    const int nseg = (T + SEG - 1) / SEG;

    for (int s = nseg - 1; s >= 0; --s) {
        const int segb = s * SEG;
        const int base = segb + lane * KPL;
        const bool full = (segb + SEG <= T);

        float A[KPL], Bl[KPL], Bs[KPL];

        if (full) {
            // rewards/dones: LDG.128 (rows 16B-aligned at base)
            const float4* r4 = (const float4*)(rrow + base);
            const float4* d4 = (const float4*)(drow + base);
            float4 ra = r4[0], rb = r4[1];
            float4 da = d4[0], db = d4[1];

            // values window [segb+1 .. segb+SEG]: coalesced scalar loads,
            // transpose through padded smem to per-lane contiguous regs.
            float vt[8];
            const float* vp = vrow + segb + 1;
            #pragma unroll
            for (int k = 0; k < 8; k++) vt[k] = __ldg(vp + k * 32 + lane);
            #pragma unroll
            for (int k = 0; k < 8; k++) {
                int i = k * 32 + lane;
                st[(i >> 3) * PAD_W + (i & 7)] = vt[k];
            }
            __syncwarp();
            float vn[KPL];
            #pragma unroll
            for (int j = 0; j < KPL; j++) vn[j] = st[lane * PAD_W + j];
            __syncwarp();

            // lambda: conflict-free LDS from transposed table
            // t = base + j  ->  q = segb/8 + lane, r = j
            const int q = (segb >> 3) + lane;
            float l[KPL];
            #pragma unroll
            for (int j = 0; j < KPL; j++) l[j] = s_lam[j * QMAX + q];

            float r[KPL] = {ra.x, ra.y, ra.z, ra.w, rb.x, rb.y, rb.z, rb.w};
            float d[KPL] = {da.x, da.y, da.z, da.w, db.x, db.y, db.z, db.w};

            #pragma unroll
            for (int j = 0; j < KPL; j++) {
                float cont = g - g * d[j];               // gamma*(1-done)
                A[j]  = cont * l[j];
                Bl[j] = fmaf(cont - A[j], vn[j], r[j]);  // cont*(1-l)*vn + r
                Bs[j] = r[j];
            }
        } else {
            #pragma unroll
            for (int j = 0; j < KPL; j++) {
                int t = base + j;
                if (t < T) {
                    float r  = rrow[t];
                    float d  = drow[t];
                    float vn = vrow[t + 1];
                    float l  = s_lam[(t & 7) * QMAX + (t >> 3)];
                    float cont = g - g * d;
                    A[j]  = cont * l;
                    Bl[j] = fmaf(cont - A[j], vn, r);
                    Bs[j] = r;
                } else {
                    A[j] = 1.0f; Bl[j] = 0.0f; Bs[j] = 0.0f;
                }
            }
        }

        // Local composition: S = m_0 ∘ ... ∘ m_{KPL-1}
        float SA = A[KPL - 1], SBl = Bl[KPL - 1], SBs = Bs[KPL - 1];
        #pragma unroll
        for (int j = KPL - 2; j >= 0; --j) {
            SBl = fmaf(A[j], SBl, Bl[j]);
            SBs = fmaf(A[j], SBs, Bs[j]);
            SA  = A[j] * SA;
        }

        // Warp inclusive suffix scan of lane maps.
        #pragma unroll
        for (int len = 1; len < 32; len <<= 1) {
            float Ao  = __shfl_down_sync(FULL_MASK, SA,  len);
            float Blo = __shfl_down_sync(FULL_MASK, SBl, len);
            float Bso = __shfl_down_sync(FULL_MASK, SBs, len);
            if (lane + len < 32) {
                SBl = fmaf(SA, Blo, SBl);
                SBs = fmaf(SA, Bso, SBs);
                SA  = SA * Ao;
            }
        }

        // Incoming state for this lane.
        float nA  = __shfl_down_sync(FULL_MASK, SA,  1);
        float nBl = __shfl_down_sync(FULL_MASK, SBl, 1);
        float nBs = __shfl_down_sync(FULL_MASK, SBs, 1);
        float xl = (lane == 31) ? c_lam : fmaf(nA, c_lam, nBl);
        float xs = (lane == 31) ? c_sum : fmaf(nA, c_sum, nBs);

        // Local expansion.
        float outl[KPL], outs[KPL];
        #pragma unroll
        for (int j = KPL - 1; j >= 0; --j) {
            xl = fmaf(A[j], xl, Bl[j]);
            xs = fmaf(A[j], xs, Bs[j]);
            outl[j] = xl;
            outs[j] = xs;
        }

        if (full) {
            // sum rows aligned -> STG.128
            float4* s4 = (float4*)(srow + base);
            s4[0] = make_float4(outs[0], outs[1], outs[2], outs[3]);
            s4[1] = make_float4(outs[4], outs[5], outs[6], outs[7]);

            // lam rows misaligned -> transpose via smem, coalesced STG.32
            #pragma unroll
            for (int j = 0; j < KPL; j++) st[lane * PAD_W + j] = outl[j];
            __syncwarp();
            float* lp = lrow + segb;
            #pragma unroll
            for (int k = 0; k < 8; k++) {
                int i = k * 32 + lane;
                lp[i] = st[(i >> 3) * PAD_W + (i & 7)];
            }
            __syncwarp();
        } else {
            #pragma unroll
            for (int j = 0; j < KPL; j++) {
                if (base + j < T) { lrow[base + j] = outl[j]; srow[base + j] = outs[j]; }
            }
        }

        c_lam = __shfl_sync(FULL_MASK, xl, 0);
        c_sum = __shfl_sync(FULL_MASK, xs, 0);
    }
}

extern "C" void kernel_launch(void* const* d_in, const int* in_sizes, int n_in,
                              void* d_out, int out_size)
{
    const float* values    = (const float*)d_in[0];
    const float* rewards   = (const float*)d_in[1];
    const float* dones     = (const float*)d_in[2];
    const float* raw_gamma = (const float*)d_in[3];
    const float* raw_lambd = (const float*)d_in[4];
    const int*   p_start   = (n_in > 5) ? (const int*)d_in[5] : nullptr;

    const int T = in_sizes[4];
    const int B = in_sizes[1] / T;

    float* out_lam = (float*)d_out;                       // B*(T+1)
    float* out_sum = (float*)d_out + (size_t)B * (T + 1); // B*T

    const int threads = WPB * 32;
    const int blocks  = (B + WPB - 1) / WPB;
    const int QMAX = (T + 7) >> 3;
    const size_t smem = (size_t)QMAX * 8 * sizeof(float);

    td_scan_kernel<<<blocks, threads, smem>>>(
        values, rewards, dones, raw_gamma, raw_lambd, p_start,
        out_lam, out_sum, B, T);
}

// round 6
// speedup vs baseline: 1.3139x; 1.2248x over previous
#include <cuda_runtime.h>
#include <cstdint>

#define FULL_MASK 0xFFFFFFFFu
#define KPL 8                 // timesteps per lane
#define SEG (32 * KPL)        // 256 timesteps per warp-segment
#define WPB 2                 // warps per block (fine-grained for load balance)
#define PAD_W 9               // padded smem words per lane (conflict-free)

// fast sigmoid via MUFU (EX2 + RCP); rel err ~1e-6, far under 1e-3 tol.
__device__ __forceinline__ float fsigmoid(float x) {
    return __fdividef(1.0f, 1.0f + __expf(-x));
}

// Precomputed per-timestep lambda and gamma (written by prep_kernel).
__device__ __align__(16) float g_lam_tab[16384];
__device__ float g_gamma_c;

__global__ void prep_kernel(const float* __restrict__ raw_gamma,
                            const float* __restrict__ raw_lambd,
                            const int*   __restrict__ p_start,
                            int T)
{
    int t = blockIdx.x * blockDim.x + threadIdx.x;
    if (t == 0) {
        // gamma = 0.99 + 0.01*(2*sig-1) = 0.98 + 0.02*sig
        g_gamma_c = 0.98f + 0.02f * fsigmoid(raw_gamma[0]);
    }
    int s0 = p_start ? p_start[0] : 0;
    if (t < T) {
        // lambda = 0.95 + 0.05*(2*sig-1) = 0.9 + 0.1*sig
        g_lam_tab[t] = fmaf(0.1f, fsigmoid(raw_lambd[s0 + t]), 0.9f);
    }
}

// One warp per batch row. Backward affine scan:
//   x_t = A_t * x_{t+1} + B_t,   A_t = g*(1-d_t)*l_t  (shared by both recurrences)
__global__ __launch_bounds__(WPB * 32)
void td_scan_kernel(const float* __restrict__ values,   // [B, T+1]
                    const float* __restrict__ rewards,  // [B, T]
                    const float* __restrict__ dones,    // [B, T]
                    float* __restrict__ out_lam,        // [B, T+1]
                    float* __restrict__ out_sum,        // [B, T]
                    int B, int T)
{
    __shared__ float stage[WPB][32 * PAD_W];

    const int lane = threadIdx.x & 31;
    const int wid  = threadIdx.x >> 5;
    const int row  = blockIdx.x * WPB + wid;
    if (row >= B) return;

    float* st = stage[wid];
    const float g = g_gamma_c;

    const float* vrow = values  + (size_t)row * (size_t)(T + 1);
    const float* rrow = rewards + (size_t)row * (size_t)T;
    const float* drow = dones   + (size_t)row * (size_t)T;
    float* lrow = out_lam + (size_t)row * (size_t)(T + 1);
    float* srow = out_sum + (size_t)row * (size_t)T;

    const float vlast = __ldcs(vrow + T);
    if (lane == 0) lrow[T] = vlast;

    float c_lam = vlast;
    float c_sum = 0.0f;

    const int nseg = (T + SEG - 1) / SEG;

    for (int s = nseg - 1; s >= 0; --s) {
        const int segb = s * SEG;
        const int base = segb + lane * KPL;
        const bool full = (segb + SEG <= T);

        float A[KPL], Bl[KPL], Bs[KPL];

        if (full) {
            // rewards/dones: streaming LDG.128 (rows 16B-aligned at base)
            float4 ra = __ldcs((const float4*)(rrow + base));
            float4 rb = __ldcs((const float4*)(rrow + base) + 1);
            float4 da = __ldcs((const float4*)(drow + base));
            float4 db = __ldcs((const float4*)(drow + base) + 1);

            // lambda table: reused across all rows -> keep cached (LDG.128)
            float4 la = *((const float4*)(g_lam_tab + base));
            float4 lb = *((const float4*)(g_lam_tab + base) + 1);

            // values window [segb+1 .. segb+SEG]: coalesced scalar streaming
            // loads, transpose through padded smem to per-lane contiguous regs.
            float vt[8];
            const float* vp = vrow + segb + 1;
            #pragma unroll
            for (int k = 0; k < 8; k++) vt[k] = __ldcs(vp + k * 32 + lane);
            #pragma unroll
            for (int k = 0; k < 8; k++) {
                int i = k * 32 + lane;
                st[(i >> 3) * PAD_W + (i & 7)] = vt[k];
            }
            __syncwarp();
            float vn[KPL];
            #pragma unroll
            for (int j = 0; j < KPL; j++) vn[j] = st[lane * PAD_W + j];
            __syncwarp();

            float r[KPL] = {ra.x, ra.y, ra.z, ra.w, rb.x, rb.y, rb.z, rb.w};
            float d[KPL] = {da.x, da.y, da.z, da.w, db.x, db.y, db.z, db.w};
            float l[KPL] = {la.x, la.y, la.z, la.w, lb.x, lb.y, lb.z, lb.w};

            #pragma unroll
            for (int j = 0; j < KPL; j++) {
                float cont = g - g * d[j];               // gamma*(1-done)
                A[j]  = cont * l[j];
                Bl[j] = fmaf(cont - A[j], vn[j], r[j]);  // cont*(1-l)*vn + r
                Bs[j] = r[j];
            }
        } else {
            #pragma unroll
            for (int j = 0; j < KPL; j++) {
                int t = base + j;
                if (t < T) {
                    float r  = rrow[t];
                    float d  = drow[t];
                    float vn = vrow[t + 1];
                    float l  = g_lam_tab[t];
                    float cont = g - g * d;
                    A[j]  = cont * l;
                    Bl[j] = fmaf(cont - A[j], vn, r);
                    Bs[j] = r;
                } else {
                    A[j] = 1.0f; Bl[j] = 0.0f; Bs[j] = 0.0f;
                }
            }
        }

        // Local composition: S = m_0 ∘ ... ∘ m_{KPL-1}
        float SA = A[KPL - 1], SBl = Bl[KPL - 1], SBs = Bs[KPL - 1];
        #pragma unroll
        for (int j = KPL - 2; j >= 0; --j) {
            SBl = fmaf(A[j], SBl, Bl[j]);
            SBs = fmaf(A[j], SBs, Bs[j]);
            SA  = A[j] * SA;
        }

        // Warp inclusive suffix scan of lane maps.
        #pragma unroll
        for (int len = 1; len < 32; len <<= 1) {
            float Ao  = __shfl_down_sync(FULL_MASK, SA,  len);
            float Blo = __shfl_down_sync(FULL_MASK, SBl, len);
            float Bso = __shfl_down_sync(FULL_MASK, SBs, len);
            if (lane + len < 32) {
                SBl = fmaf(SA, Blo, SBl);
                SBs = fmaf(SA, Bso, SBs);
                SA  = SA * Ao;
            }
        }

        // Incoming state for this lane.
        float nA  = __shfl_down_sync(FULL_MASK, SA,  1);
        float nBl = __shfl_down_sync(FULL_MASK, SBl, 1);
        float nBs = __shfl_down_sync(FULL_MASK, SBs, 1);
        float xl = (lane == 31) ? c_lam : fmaf(nA, c_lam, nBl);
        float xs = (lane == 31) ? c_sum : fmaf(nA, c_sum, nBs);

        // Local expansion.
        float outl[KPL], outs[KPL];
        #pragma unroll
        for (int j = KPL - 1; j >= 0; --j) {
            xl = fmaf(A[j], xl, Bl[j]);
            xs = fmaf(A[j], xs, Bs[j]);
            outl[j] = xl;
            outs[j] = xs;
        }

        if (full) {
            // sum rows aligned -> streaming STG.128
            float4* s4 = (float4*)(srow + base);
            __stcs(s4,     make_float4(outs[0], outs[1], outs[2], outs[3]));
            __stcs(s4 + 1, make_float4(outs[4], outs[5], outs[6], outs[7]));

            // lam rows misaligned -> transpose via smem, coalesced STG.32
            #pragma unroll
            for (int j = 0; j < KPL; j++) st[lane * PAD_W + j] = outl[j];
            __syncwarp();
            float* lp = lrow + segb;
            #pragma unroll
            for (int k = 0; k < 8; k++) {
                int i = k * 32 + lane;
                __stcs(lp + i, st[(i >> 3) * PAD_W + (i & 7)]);
            }
            __syncwarp();
        } else {
            #pragma unroll
            for (int j = 0; j < KPL; j++) {
                if (base + j < T) { lrow[base + j] = outl[j]; srow[base + j] = outs[j]; }
            }
        }

        c_lam = __shfl_sync(FULL_MASK, xl, 0);
        c_sum = __shfl_sync(FULL_MASK, xs, 0);
    }
}

extern "C" void kernel_launch(void* const* d_in, const int* in_sizes, int n_in,
                              void* d_out, int out_size)
{
    const float* values    = (const float*)d_in[0];
    const float* rewards   = (const float*)d_in[1];
    const float* dones     = (const float*)d_in[2];
    const float* raw_gamma = (const float*)d_in[3];
    const float* raw_lambd = (const float*)d_in[4];
    const int*   p_start   = (n_in > 5) ? (const int*)d_in[5] : nullptr;

    const int T = in_sizes[4];
    const int B = in_sizes[1] / T;

    float* out_lam = (float*)d_out;                       // B*(T+1)
    float* out_sum = (float*)d_out + (size_t)B * (T + 1); // B*T

    prep_kernel<<<(T + 255) / 256, 256>>>(raw_gamma, raw_lambd, p_start, T);

    const int threads = WPB * 32;
    const int blocks  = (B + WPB - 1) / WPB;

    td_scan_kernel<<<blocks, threads>>>(
        values, rewards, dones, out_lam, out_sum, B, T);
}